// round 8
// baseline (speedup 1.0000x reference)
#include <cuda_runtime.h>
#include <cuda_bf16.h>
#include <cstdint>

namespace {
constexpr int Sd = 2048, Dd = 64, QT = 64, CH = 64, NCH = Sd / CH, NT = 128;
constexpr int PIT = 72;                      // bf16 row pitch (conflict-free LDSM)
constexpr int TILE = QT * PIT * 2;           // 9216 bytes per bf16 tile
constexpr int SQH = 0, SQL = TILE;           // Q hi/lo
constexpr int SK = 2 * TILE;                 // K: 2 bufs x (hi+lo)
constexpr int SV = SK + 4 * TILE;            // V: 2 bufs x (hi+lo)
constexpr int SMEM_BYTES = SV + 4 * TILE;    // 92160

__device__ __forceinline__ uint32_t smem_u32(const void* p) {
    uint32_t a;
    asm("{ .reg .u64 t; cvta.to.shared.u64 t, %1; cvt.u32.u64 %0, t; }"
        : "=r"(a) : "l"(p));
    return a;
}
__device__ __forceinline__ uint32_t pack2(float a, float b) {  // lo=a, hi=b
    uint32_t r;
    asm("cvt.rn.bf16x2.f32 %0, %1, %2;" : "=r"(r) : "f"(b), "f"(a));
    return r;
}
__device__ __forceinline__ float bfr(float x) {
    return __bfloat162float(__float2bfloat16(x));
}
__device__ __forceinline__ void ldm_x4(uint32_t a, uint32_t* r) {
    asm volatile("ldmatrix.sync.aligned.m8n8.x4.shared.b16 {%0,%1,%2,%3}, [%4];"
                 : "=r"(r[0]), "=r"(r[1]), "=r"(r[2]), "=r"(r[3]) : "r"(a));
}
__device__ __forceinline__ void ldm_x2(uint32_t a, uint32_t* r) {
    asm volatile("ldmatrix.sync.aligned.m8n8.x2.shared.b16 {%0,%1}, [%2];"
                 : "=r"(r[0]), "=r"(r[1]) : "r"(a));
}
__device__ __forceinline__ void ldm_x2t(uint32_t a, uint32_t* r) {
    asm volatile("ldmatrix.sync.aligned.m8n8.x2.trans.shared.b16 {%0,%1}, [%2];"
                 : "=r"(r[0]), "=r"(r[1]) : "r"(a));
}
__device__ __forceinline__ void mma_bf16(float* d, const uint32_t* a,
                                         const uint32_t* b) {
    asm volatile(
        "mma.sync.aligned.m16n8k16.row.col.f32.bf16.bf16.f32 "
        "{%0,%1,%2,%3}, {%4,%5,%6,%7}, {%8,%9}, {%0,%1,%2,%3};"
        : "+f"(d[0]), "+f"(d[1]), "+f"(d[2]), "+f"(d[3])
        : "r"(a[0]), "r"(a[1]), "r"(a[2]), "r"(a[3]), "r"(b[0]), "r"(b[1]));
}

// [64 x 64] fp32 -> bf16 hi/lo tiles, pitch-72 rows.
__device__ __forceinline__ void load_conv(const float* __restrict__ src,
                                          char* sm, int offH, int offL,
                                          int t, float scale) {
    #pragma unroll
    for (int i = 0; i < 8; ++i) {
        const int idx4 = t + NT * i;
        const int row = idx4 >> 4, c4 = (idx4 & 15) << 2;
        float4 v = *(const float4*)(src + (size_t)idx4 * 4);
        v.x *= scale; v.y *= scale; v.z *= scale; v.w *= scale;
        const float hx = bfr(v.x), hy = bfr(v.y), hz = bfr(v.z), hw = bfr(v.w);
        const int boff = (row * PIT + c4) * 2;
        *(uint2*)(sm + offH + boff) = make_uint2(pack2(v.x, v.y), pack2(v.z, v.w));
        *(uint2*)(sm + offL + boff) =
            make_uint2(pack2(v.x - hx, v.y - hy), pack2(v.z - hz, v.w - hw));
    }
}
} // namespace

__global__ void __launch_bounds__(NT)
attn_mma_kernel(const float* __restrict__ Q, const float* __restrict__ K,
                const float* __restrict__ V, const float* __restrict__ Mk,
                float* __restrict__ OC, float* __restrict__ OA)
{
    extern __shared__ char smem[];
    const uint32_t sb = smem_u32(smem);

    const int t = threadIdx.x, w = t >> 5, l = t & 31;
    const int gid = l >> 2, qd = l & 3;
    const int qt = blockIdx.x, bh = blockIdx.y;

    const float* Qb = Q + ((long)bh * Sd + qt * QT) * Dd;
    const float* Kb = K + (long)bh * Sd * Dd;
    const float* Vb = V + (long)bh * Sd * Dd;
    const float* Mb = Mk + ((long)bh * Sd + qt * QT) * Sd;
    float*       Ab = OA + ((long)bh * Sd + qt * QT) * Sd;
    float*       Cb = OC + ((long)bh * Sd + qt * QT) * Dd;

    // Stage Q (x 1/8) and chunk 0 of K/V.
    load_conv(Qb, smem, SQH, SQL, t, 0.125f);
    load_conv(Kb, smem, SK, SK + TILE, t, 1.0f);
    load_conv(Vb, smem, SV, SV + TILE, t, 1.0f);
    __syncthreads();

    // Q fragments (A operand), 4 k-tiles, hi/lo.
    uint32_t qh[4][4], ql[4][4];
    {
        const int rowb = ((16 * w + (l & 15)) * PIT + ((l >> 4) << 3)) * 2;
        #pragma unroll
        for (int kt = 0; kt < 4; ++kt) {
            ldm_x4(sb + SQH + rowb + kt * 32, qh[kt]);
            ldm_x4(sb + SQL + rowb + kt * 32, ql[kt]);
        }
    }

    float ctx[8][4];
    #pragma unroll
    for (int d = 0; d < 8; ++d)
        { ctx[d][0] = 0.f; ctx[d][1] = 0.f; ctx[d][2] = 0.f; ctx[d][3] = 0.f; }
    float rs0 = 0.f, rs1 = 0.f;

    const int l2 = l & 15;
    const int koff = ((l2 & 7) * PIT + ((l2 >> 3) << 3)) * 2;
    const int voff = (l2 * PIT) * 2;

    const float* mrow = Mb + (long)(16 * w + gid) * Sd + 2 * qd;
    float*       arow = Ab + (long)(16 * w + gid) * Sd + 2 * qd;

    for (int c = 0; c < NCH; ++c) {
        const int buf = c & 1;
        if (c + 1 < NCH) {
            load_conv(Kb + (long)(c + 1) * CH * Dd, smem,
                      SK + (buf ^ 1) * 2 * TILE, SK + (buf ^ 1) * 2 * TILE + TILE,
                      t, 1.0f);
            load_conv(Vb + (long)(c + 1) * CH * Dd, smem,
                      SV + (buf ^ 1) * 2 * TILE, SV + (buf ^ 1) * 2 * TILE + TILE,
                      t, 1.0f);
        }

        const uint32_t kh_base = sb + SK + buf * 2 * TILE + koff;
        const uint32_t kl_base = kh_base + TILE;
        const uint32_t vh_base = sb + SV + buf * 2 * TILE + voff;
        const uint32_t vl_base = vh_base + TILE;
        const int cb = c * CH;

        uint32_t Ph[16], Pl[16];
        #pragma unroll
        for (int nt = 0; nt < 8; ++nt) {
            float s[4] = {0.f, 0.f, 0.f, 0.f};
            #pragma unroll
            for (int kt = 0; kt < 4; ++kt) {
                const uint32_t off = (uint32_t)(nt * 8 * PIT * 2 + kt * 32);
                uint32_t kh[2], kl[2];
                ldm_x2(kh_base + off, kh);
                ldm_x2(kl_base + off, kl);
                mma_bf16(s, qh[kt], kh);
                mma_bf16(s, qh[kt], kl);
                mma_bf16(s, ql[kt], kh);
            }
            const float2 m0 = *(const float2*)(mrow + cb + nt * 8);
            const float2 m1 = *(const float2*)(mrow + cb + nt * 8 + 8 * (long)Sd);
            const float e0 = __expf(s[0] + m0.x), e1 = __expf(s[1] + m0.y);
            const float e2 = __expf(s[2] + m1.x), e3 = __expf(s[3] + m1.y);
            rs0 += e0 + e1; rs1 += e2 + e3;
            *(float2*)(arow + cb + nt * 8) = make_float2(e0, e1);
            *(float2*)(arow + cb + nt * 8 + 8 * (long)Sd) = make_float2(e2, e3);
            const float h0 = bfr(e0), h1 = bfr(e1), h2 = bfr(e2), h3 = bfr(e3);
            Ph[2 * nt]     = pack2(e0, e1);
            Ph[2 * nt + 1] = pack2(e2, e3);
            Pl[2 * nt]     = pack2(e0 - h0, e1 - h1);
            Pl[2 * nt + 1] = pack2(e2 - h2, e3 - h3);
        }

        #pragma unroll
        for (int kt = 0; kt < 4; ++kt) {
            const uint32_t* ah = Ph + 4 * kt;
            const uint32_t* al = Pl + 4 * kt;
            const uint32_t vrow = (uint32_t)(kt * 16 * PIT * 2);
            #pragma unroll
            for (int dt = 0; dt < 8; ++dt) {
                uint32_t vh[2], vl[2];
                ldm_x2t(vh_base + vrow + dt * 16, vh);
                ldm_x2t(vl_base + vrow + dt * 16, vl);
                mma_bf16(ctx[dt], ah, vh);
                mma_bf16(ctx[dt], ah, vl);
                mma_bf16(ctx[dt], al, vh);
            }
        }
        __syncthreads();
    }

    // Rowsum reduce across quad lanes; publish 1/sum to smem.
    #pragma unroll
    for (int o = 1; o < 4; o <<= 1) {
        rs0 += __shfl_xor_sync(0xffffffffu, rs0, o);
        rs1 += __shfl_xor_sync(0xffffffffu, rs1, o);
    }
    const float inv0 = 1.0f / rs0, inv1 = 1.0f / rs1;
    float* sinv = (float*)smem;   // Q tile region no longer needed
    if (qd == 0) {
        sinv[16 * w + gid]     = inv0;
        sinv[16 * w + gid + 8] = inv1;
    }

    // Normalized context store.
    {
        float* crow = Cb + (long)(16 * w + gid) * Dd + 2 * qd;
        #pragma unroll
        for (int dt = 0; dt < 8; ++dt) {
            *(float2*)(crow + dt * 8) =
                make_float2(ctx[dt][0] * inv0, ctx[dt][1] * inv0);
            *(float2*)(crow + dt * 8 + 8 * Dd) =
                make_float2(ctx[dt][2] * inv1, ctx[dt][3] * inv1);
        }
    }
    __syncthreads();

    // In-kernel attention normalization: re-scan own 512KB tile (L2-warm).
    {
        float4* At = (float4*)Ab;
        constexpr int NF4 = QT * Sd / 4;      // 32768 float4
        #pragma unroll 4
        for (int i = t; i < NF4; i += NT) {
            const int row = i >> 9;           // 512 float4 per row
            float4 v = At[i];
            const float s = sinv[row];
            v.x *= s; v.y *= s; v.z *= s; v.w *= s;
            At[i] = v;
        }
    }
}

extern "C" void kernel_launch(void* const* d_in, const int* in_sizes, int n_in,
                              void* d_out, int out_size) {
    const float* Q = (const float*)d_in[0];
    const float* K = (const float*)d_in[1];
    const float* V = (const float*)d_in[2];
    const float* M = (const float*)d_in[3];

    float* ctx  = (float*)d_out;
    float* attn = (float*)d_out + (size_t)2 * 16 * 2048 * 64;

    cudaFuncSetAttribute(attn_mma_kernel,
                         cudaFuncAttributeMaxDynamicSharedMemorySize, SMEM_BYTES);

    dim3 grid(Sd / QT, 32);   // (32, 32)
    attn_mma_kernel<<<grid, NT, SMEM_BYTES>>>(Q, K, V, M, ctx, attn);
}

// round 9
// speedup vs baseline: 1.5022x; 1.5022x over previous
#include <cuda_runtime.h>
#include <cuda_bf16.h>
#include <cstdint>

namespace {
constexpr int Sd = 2048, Dd = 64, QT = 64, CH = 64, NCH = Sd / CH, NT = 256;
constexpr int PIT = 72;                      // bf16 row pitch (conflict-free LDSM)
constexpr int TILE = QT * PIT * 2;           // 9216 bytes per bf16 tile
constexpr int SQH = 0, SQL = TILE;           // Q hi/lo
constexpr int SK = 2 * TILE;                 // K: 2 bufs x (hi+lo)
constexpr int SV = SK + 4 * TILE;            // V: 2 bufs x (hi+lo)
constexpr int SMEM_BYTES = SV + 4 * TILE;    // 92160

__device__ float g_inv[65536];

__device__ __forceinline__ uint32_t smem_u32(const void* p) {
    uint32_t a;
    asm("{ .reg .u64 t; cvta.to.shared.u64 t, %1; cvt.u32.u64 %0, t; }"
        : "=r"(a) : "l"(p));
    return a;
}
__device__ __forceinline__ uint32_t pack2(float a, float b) {  // lo=a, hi=b
    uint32_t r;
    asm("cvt.rn.bf16x2.f32 %0, %1, %2;" : "=r"(r) : "f"(b), "f"(a));
    return r;
}
__device__ __forceinline__ float bfr(float x) {
    return __bfloat162float(__float2bfloat16(x));
}
__device__ __forceinline__ void ldm_x4(uint32_t a, uint32_t* r) {
    asm volatile("ldmatrix.sync.aligned.m8n8.x4.shared.b16 {%0,%1,%2,%3}, [%4];"
                 : "=r"(r[0]), "=r"(r[1]), "=r"(r[2]), "=r"(r[3]) : "r"(a));
}
__device__ __forceinline__ void ldm_x2(uint32_t a, uint32_t* r) {
    asm volatile("ldmatrix.sync.aligned.m8n8.x2.shared.b16 {%0,%1}, [%2];"
                 : "=r"(r[0]), "=r"(r[1]) : "r"(a));
}
__device__ __forceinline__ void ldm_x2t(uint32_t a, uint32_t* r) {
    asm volatile("ldmatrix.sync.aligned.m8n8.x2.trans.shared.b16 {%0,%1}, [%2];"
                 : "=r"(r[0]), "=r"(r[1]) : "r"(a));
}
__device__ __forceinline__ void mma_bf16(float* d, const uint32_t* a,
                                         const uint32_t* b) {
    asm volatile(
        "mma.sync.aligned.m16n8k16.row.col.f32.bf16.bf16.f32 "
        "{%0,%1,%2,%3}, {%4,%5,%6,%7}, {%8,%9}, {%0,%1,%2,%3};"
        : "+f"(d[0]), "+f"(d[1]), "+f"(d[2]), "+f"(d[3])
        : "r"(a[0]), "r"(a[1]), "r"(a[2]), "r"(a[3]), "r"(b[0]), "r"(b[1]));
}

// [64 x 64] fp32 -> bf16 hi/lo tiles, pitch-72 rows. 256 threads.
__device__ __forceinline__ void load_conv(const float* __restrict__ src,
                                          char* sm, int offH, int offL,
                                          int t, float scale) {
    #pragma unroll
    for (int i = 0; i < 4; ++i) {
        const int idx4 = t + NT * i;
        const int row = idx4 >> 4, c4 = (idx4 & 15) << 2;
        float4 v = *(const float4*)(src + (size_t)idx4 * 4);
        v.x *= scale; v.y *= scale; v.z *= scale; v.w *= scale;
        const float hx = bfr(v.x), hy = bfr(v.y), hz = bfr(v.z), hw = bfr(v.w);
        const int boff = (row * PIT + c4) * 2;
        *(uint2*)(sm + offH + boff) = make_uint2(pack2(v.x, v.y), pack2(v.z, v.w));
        *(uint2*)(sm + offL + boff) =
            make_uint2(pack2(v.x - hx, v.y - hy), pack2(v.z - hz, v.w - hw));
    }
}
} // namespace

__global__ void __launch_bounds__(NT, 2)
attn_mma_kernel(const float* __restrict__ Q, const float* __restrict__ K,
                const float* __restrict__ V, const float* __restrict__ Mk,
                float* __restrict__ OC, float* __restrict__ OA)
{
    extern __shared__ char smem[];
    const uint32_t sb = smem_u32(smem);

    const int t = threadIdx.x, w = t >> 5, l = t & 31;
    const int qw = w & 3;        // q-row group: rows 16*qw..16*qw+15
    const int kh = w >> 2;       // k-half within chunk: cols kh*32..kh*32+31
    const int gid = l >> 2, qd = l & 3;
    const int qt = blockIdx.x, bh = blockIdx.y;

    const float* Qb = Q + ((long)bh * Sd + qt * QT) * Dd;
    const float* Kb = K + (long)bh * Sd * Dd;
    const float* Vb = V + (long)bh * Sd * Dd;
    const float* Mb = Mk + ((long)bh * Sd + qt * QT) * Sd;
    float*       Ab = OA + ((long)bh * Sd + qt * QT) * Sd;
    float*       Cb = OC + ((long)bh * Sd + qt * QT) * Dd;

    load_conv(Qb, smem, SQH, SQL, t, 0.125f);
    load_conv(Kb, smem, SK, SK + TILE, t, 1.0f);
    load_conv(Vb, smem, SV, SV + TILE, t, 1.0f);
    __syncthreads();

    // Q fragments (A operand), 4 d-tiles, hi/lo (same for both k-halves).
    uint32_t qh[4][4], ql[4][4];
    {
        const int rowb = ((16 * qw + (l & 15)) * PIT + ((l >> 4) << 3)) * 2;
        #pragma unroll
        for (int kt = 0; kt < 4; ++kt) {
            ldm_x4(sb + SQH + rowb + kt * 32, qh[kt]);
            ldm_x4(sb + SQL + rowb + kt * 32, ql[kt]);
        }
    }

    float ctx[8][4];
    #pragma unroll
    for (int d = 0; d < 8; ++d)
        { ctx[d][0] = 0.f; ctx[d][1] = 0.f; ctx[d][2] = 0.f; ctx[d][3] = 0.f; }
    float rs0 = 0.f, rs1 = 0.f;

    const int l2 = l & 15;
    const int koff = ((l2 & 7) * PIT + ((l2 >> 3) << 3)) * 2;
    const int voff = (l2 * PIT) * 2;

    const float* mrow = Mb + (long)(16 * qw + gid) * Sd + kh * 32 + 2 * qd;
    float*       arow = Ab + (long)(16 * qw + gid) * Sd + kh * 32 + 2 * qd;

    for (int c = 0; c < NCH; ++c) {
        const int buf = c & 1;
        if (c + 1 < NCH) {
            load_conv(Kb + (long)(c + 1) * CH * Dd, smem,
                      SK + (buf ^ 1) * 2 * TILE, SK + (buf ^ 1) * 2 * TILE + TILE,
                      t, 1.0f);
            load_conv(Vb + (long)(c + 1) * CH * Dd, smem,
                      SV + (buf ^ 1) * 2 * TILE, SV + (buf ^ 1) * 2 * TILE + TILE,
                      t, 1.0f);
        }

        const uint32_t kh_base = sb + SK + buf * 2 * TILE + koff;
        const uint32_t kl_base = kh_base + TILE;
        const uint32_t vh_base = sb + SV + buf * 2 * TILE + voff;
        const uint32_t vl_base = vh_base + TILE;
        const int cb = c * CH;

        uint32_t Ph[8], Pl[8];
        #pragma unroll
        for (int nt = 0; nt < 4; ++nt) {           // this warp's 4 n-tiles
            const int ntg = kh * 4 + nt;
            float sA[4] = {0.f,0.f,0.f,0.f};
            float sB[4] = {0.f,0.f,0.f,0.f};
            float sC[4] = {0.f,0.f,0.f,0.f};
            #pragma unroll
            for (int kt = 0; kt < 4; ++kt) {
                const uint32_t off = (uint32_t)(ntg * 8 * PIT * 2 + kt * 32);
                uint32_t kfh[2], kfl[2];
                ldm_x2(kh_base + off, kfh);
                ldm_x2(kl_base + off, kfl);
                mma_bf16(sA, qh[kt], kfh);
                mma_bf16(sB, qh[kt], kfl);
                mma_bf16(sC, ql[kt], kfh);
            }
            const float2 m0 = *(const float2*)(mrow + cb + nt * 8);
            const float2 m1 = *(const float2*)(mrow + cb + nt * 8 + 8 * (long)Sd);
            const float e0 = __expf((sA[0] + sB[0]) + (sC[0] + m0.x));
            const float e1 = __expf((sA[1] + sB[1]) + (sC[1] + m0.y));
            const float e2 = __expf((sA[2] + sB[2]) + (sC[2] + m1.x));
            const float e3 = __expf((sA[3] + sB[3]) + (sC[3] + m1.y));
            rs0 += e0 + e1; rs1 += e2 + e3;
            *(float2*)(arow + cb + nt * 8) = make_float2(e0, e1);
            *(float2*)(arow + cb + nt * 8 + 8 * (long)Sd) = make_float2(e2, e3);
            const float h0 = bfr(e0), h1 = bfr(e1), h2 = bfr(e2), h3 = bfr(e3);
            Ph[2 * nt]     = pack2(e0, e1);
            Ph[2 * nt + 1] = pack2(e2, e3);
            Pl[2 * nt]     = pack2(e0 - h0, e1 - h1);
            Pl[2 * nt + 1] = pack2(e2 - h2, e3 - h3);
        }

        #pragma unroll
        for (int kt = 0; kt < 2; ++kt) {           // this warp's 2 k-tiles of PV
            const int ktg = kh * 2 + kt;
            const uint32_t* ah = Ph + 4 * kt;
            const uint32_t* al = Pl + 4 * kt;
            const uint32_t vrow = (uint32_t)(ktg * 16 * PIT * 2);
            #pragma unroll
            for (int dt = 0; dt < 8; ++dt) {
                uint32_t vfh[2], vfl[2];
                ldm_x2t(vh_base + vrow + dt * 16, vfh);
                ldm_x2t(vl_base + vrow + dt * 16, vfl);
                mma_bf16(ctx[dt], ah, vfh);
                mma_bf16(ctx[dt], ah, vfl);
                mma_bf16(ctx[dt], al, vfh);
            }
        }
        __syncthreads();
    }

    // rowsum: quad-reduce, then combine the two k-halves through smem.
    #pragma unroll
    for (int o = 1; o < 4; o <<= 1) {
        rs0 += __shfl_xor_sync(0xffffffffu, rs0, o);
        rs1 += __shfl_xor_sync(0xffffffffu, rs1, o);
    }
    float* srs = (float*)smem;            // [2][64]
    if (qd == 0) {
        srs[kh * 64 + 16 * qw + gid]     = rs0;
        srs[kh * 64 + 16 * qw + gid + 8] = rs1;
    }
    __syncthreads();
    const int r0 = 16 * qw + gid;
    const float inv0 = 1.0f / (srs[r0] + srs[64 + r0]);
    const float inv1 = 1.0f / (srs[r0 + 8] + srs[64 + r0 + 8]);
    if (qd == 0 && kh == 0) {
        const int grow = bh * Sd + qt * QT + r0;
        g_inv[grow]     = inv0;
        g_inv[grow + 8] = inv1;
    }

    // ctx: half 1 publishes partials (pitch-68), half 0 adds + stores.
    float* cs = (float*)(smem + 1024);    // 64 x 68 floats
    if (kh == 1) {
        #pragma unroll
        for (int dt = 0; dt < 8; ++dt) {
            *(float2*)(cs + r0 * 68 + dt * 8 + 2 * qd) =
                make_float2(ctx[dt][0], ctx[dt][1]);
            *(float2*)(cs + (r0 + 8) * 68 + dt * 8 + 2 * qd) =
                make_float2(ctx[dt][2], ctx[dt][3]);
        }
    }
    __syncthreads();
    if (kh == 0) {
        float* crow = Cb + (long)r0 * Dd + 2 * qd;
        #pragma unroll
        for (int dt = 0; dt < 8; ++dt) {
            const float2 p0 = *(const float2*)(cs + r0 * 68 + dt * 8 + 2 * qd);
            const float2 p1 = *(const float2*)(cs + (r0 + 8) * 68 + dt * 8 + 2 * qd);
            *(float2*)(crow + dt * 8) =
                make_float2((ctx[dt][0] + p0.x) * inv0, (ctx[dt][1] + p0.y) * inv0);
            *(float2*)(crow + dt * 8 + 8 * Dd) =
                make_float2((ctx[dt][2] + p1.x) * inv1, (ctx[dt][3] + p1.y) * inv1);
        }
    }
}

__global__ void __launch_bounds__(256, 8)
attn_norm_kernel(float* __restrict__ A)
{
    const size_t i = ((size_t)blockIdx.x * 256 + threadIdx.x) * 4;
    const int row = (int)(i >> 11);
    float4 v = *(float4*)(A + i);
    const float s = g_inv[row];
    v.x *= s; v.y *= s; v.z *= s; v.w *= s;
    *(float4*)(A + i) = v;
}

extern "C" void kernel_launch(void* const* d_in, const int* in_sizes, int n_in,
                              void* d_out, int out_size) {
    const float* Q = (const float*)d_in[0];
    const float* K = (const float*)d_in[1];
    const float* V = (const float*)d_in[2];
    const float* M = (const float*)d_in[3];

    float* ctx  = (float*)d_out;
    float* attn = (float*)d_out + (size_t)2 * 16 * 2048 * 64;

    cudaFuncSetAttribute(attn_mma_kernel,
                         cudaFuncAttributeMaxDynamicSharedMemorySize, SMEM_BYTES);

    dim3 grid(Sd / QT, 32);   // (32, 32)
    attn_mma_kernel<<<grid, NT, SMEM_BYTES>>>(Q, K, V, M, ctx, attn);

    const size_t total4 = (size_t)32 * 2048 * 2048 / 4;
    attn_norm_kernel<<<(unsigned)(total4 / 256), 256>>>(attn);
}